// round 4
// baseline (speedup 1.0000x reference)
#include <cuda_runtime.h>
#include <cuda_bf16.h>

// Problem constants (fixed by setup_inputs)
#define SS 2000   // filtration points
#define PP 2500   // sample points
#define RR 5      // bars per point
#define NB 256    // buckets for counting sort

// Output layout (flattened concatenation, floats):
//   bars_stack : [0, 25000)
//   gm0        : [25000, 50025000)           (R,P,2S)
//   gc0        : [50025000, 50050000)        (R,P,2)
//   gm1        : [50050000, 100050000)
//   gc1        : [100050000, 100075000)

// Bucket-sorted filtration tables (built once per launch by bin_kernel)
__device__ float g_kx[SS], g_cx[SS];   // sorted-by-fx : key=fx, companion=fy
__device__ int   g_sx[SS];
__device__ float g_ky[SS], g_cy[SS];   // sorted-by-fy : key=fy, companion=fx
__device__ int   g_sy[SS];
__device__ int   g_ofx[NB + 1], g_ofy[NB + 1];

// One block per axis (blockIdx.x = axis), parallel prefix scan.
__global__ void bin_kernel(const float* __restrict__ filt)
{
    __shared__ int hist[NB];
    __shared__ int scan[NB];
    __shared__ int cur[NB];
    int t = threadIdx.x;
    int axis = blockIdx.x;

    hist[t] = 0;
    __syncthreads();
    for (int s = t; s < SS; s += NB) {
        float v = filt[2 * s + axis];
        int b = min(NB - 1, max(0, (int)floorf(v * (float)NB)));
        atomicAdd(&hist[b], 1);
    }
    __syncthreads();
    // inclusive scan (Hillis-Steele)
    int v = hist[t];
    scan[t] = v;
    __syncthreads();
    #pragma unroll
    for (int ofs = 1; ofs < NB; ofs <<= 1) {
        int add = (t >= ofs) ? scan[t - ofs] : 0;
        __syncthreads();
        scan[t] += add;
        __syncthreads();
    }
    int excl = scan[t] - v;
    int* offs = axis ? g_ofy : g_ofx;
    offs[t] = excl;
    if (t == NB - 1) offs[NB] = scan[t];
    cur[t] = excl;
    __syncthreads();
    for (int s = t; s < SS; s += NB) {
        float kv = filt[2 * s + axis];
        float cv = filt[2 * s + (1 - axis)];
        int b = min(NB - 1, max(0, (int)floorf(kv * (float)NB)));
        int pos = atomicAdd(&cur[b], 1);
        if (axis == 0) { g_kx[pos] = kv; g_cx[pos] = cv; g_sx[pos] = s; }
        else           { g_ky[pos] = kv; g_cy[pos] = cv; g_sy[pos] = s; }
    }
}

// Block per p, 256 threads. Two phases, ONE barrier:
//   1) burst-zero all 10 gm rows (160KB, coalesced float4)
//   2) sparse scatter over 100 (combo x range) units spread over 8 warps
__global__ __launch_bounds__(256) void grad_kernel(
    const float* __restrict__ bars0,
    const float* __restrict__ bars1,
    const float* __restrict__ pts,
    float* __restrict__ out)
{
    const size_t GM0 = 2ull * PP * RR;                     // 25000
    const size_t GC0 = GM0 + (size_t)RR * PP * 2 * SS;     // 50025000
    const size_t GM1 = GC0 + (size_t)RR * PP * 2;          // 50050000
    const size_t GC1 = GM1 + (size_t)RR * PP * 2 * SS;     // 100050000

    int p = blockIdx.x;
    int t = threadIdx.x;
    int warp = t >> 5, lane = t & 31;

    __shared__ float    sscale[10];
    __shared__ unsigned sflags[10];

    float2 pt = ((const float2*)pts)[p];
    float ptx = pt.x, pty = pt.y;
    float psum = __fadd_rn(ptx, pty);

    if (t < 10) {
        int h = t / RR, r = t % RR;
        float bar = (h ? bars1 : bars0)[p * RR + r];
        out[(size_t)h * PP * RR + (size_t)p * RR + r] = bar;   // bars_stack
        sscale[t] = __fadd_rn(bar, 0.01f);                     // scale = bar + GRID_RES
        sflags[t] = 0u;
    }

    // ---- Phase 1: burst-zero all 10 rows (no barriers in between) ----
    const float4 z4 = make_float4(0.f, 0.f, 0.f, 0.f);
    #pragma unroll
    for (int c = 0; c < 10; ++c) {
        size_t rowbase = (c < RR ? GM0 : GM1) +
                         ((size_t)(c % RR) * PP + p) * (size_t)(2 * SS);
        float4* row4 = (float4*)(out + rowbase);
        #pragma unroll
        for (int i = 0; i < 4; ++i) {
            int idx = t + i * 256;
            if (idx < SS / 2) row4[idx] = z4;
        }
    }
    __syncthreads();   // orders zeros (and sscale/sflags) before scatter

    // ---- Phase 2: sparse scatter. 100 units = combo(10) x (axis,k)(10) ----
    for (int u = warp; u < 100; u += 8) {
        int   c    = u / 10;          // combo: h = c/RR, r = c%RR
        int   rid  = u % 10;          // axis*5 + (k+2)
        int   axis = rid / 5;
        float kf   = (float)(rid % 5 - 2);
        float sc   = sscale[c];
        size_t rowbase = (c < RR ? GM0 : GM1) +
                         ((size_t)(c % RR) * PP + p) * (size_t)(2 * SS);
        float myp  = axis ? pty : ptx;       // line anchor for this axis
        float otp  = axis ? ptx : pty;       // companion axis anchor
        // Exact reference arithmetic (mul then add, no FMA fusion):
        float line  = __fadd_rn(__fmul_rn(kf, sc), myp);
        float lastc = __fadd_rn(__fmul_rn(2.0f, sc), otp); // last_{other axis}
        // Widened bucket range (max tol = 0.01001 < 0.0101)
        int b0 = min(NB - 1, max(0, (int)floorf((line - 0.0101f) * (float)NB)));
        int b1 = min(NB - 1, max(0, (int)floorf((line + 0.0101f) * (float)NB)));
        const int*   offs = axis ? g_ofy : g_ofx;
        const float* keys = axis ? g_ky  : g_kx;
        const float* comp = axis ? g_cy  : g_cx;
        const int*   sarr = axis ? g_sy  : g_sx;
        int lo = __ldg(&offs[b0]);
        int hi = __ldg(&offs[b1 + 1]);
        for (int i = lo + lane; i < hi; i += 32) {
            float key = __ldg(&keys[i]);                       // f_axis[s]
            float tol = __fadd_rn(0.01f, __fmul_rn(1e-5f, fabsf(key)));
            if (fabsf(__fadd_rn(line, -key)) > tol) continue;  // close?
            float other = __ldg(&comp[i]);                     // f_other[s]
            if (!(other <= lastc)) continue;                   // cond gate
            float fsum = __fadd_rn(key, other);                // fx+fy (commutes)
            if (fsum == psum) continue;                        // value 0
            bool above = fsum > psum;
            int s = __ldg(&sarr[i]);
            out[rowbase + 2 * (size_t)s + (size_t)axis] = above ? 1.0f : -1.0f;
            unsigned bits = (axis ? 4u : 1u) << (above ? 0 : 1);
            atomicOr(&sflags[c], bits);
        }
    }
    __syncthreads();

    if (t < 10) {
        unsigned fl = sflags[t];
        // cx = anyUpper ? -1 : anyLower ? 1 : 0   (signs flipped vs gm)
        float cxv = (fl & 1u) ? -1.0f : ((fl & 2u) ? 1.0f : 0.0f);
        float cyv = (fl & 4u) ? -1.0f : ((fl & 8u) ? 1.0f : 0.0f);
        size_t gcb = (t < RR ? GC0 : GC1) + ((size_t)(t % RR) * PP + p) * 2;
        out[gcb]     = cxv;
        out[gcb + 1] = cyv;
    }
}

extern "C" void kernel_launch(void* const* d_in, const int* in_sizes, int n_in,
                              void* d_out, int out_size)
{
    (void)in_sizes; (void)n_in; (void)out_size;
    const float* filtration = (const float*)d_in[0];   // (S,2)
    const float* bars0      = (const float*)d_in[1];   // (P,R)
    const float* bars1      = (const float*)d_in[2];   // (P,R)
    const float* pts        = (const float*)d_in[3];   // (P,2)
    float* out = (float*)d_out;

    bin_kernel<<<2, NB>>>(filtration);
    grad_kernel<<<PP, 256>>>(bars0, bars1, pts, out);
}

// round 5
// speedup vs baseline: 2.0700x; 2.0700x over previous
#include <cuda_runtime.h>
#include <cuda_bf16.h>

// Problem constants (fixed by setup_inputs)
#define SS 2000   // filtration points
#define PP 2500   // sample points
#define RR 5      // bars per point
#define NB 256    // buckets for counting sort

// Output layout (flattened concatenation, floats):
//   bars_stack : [0, 25000)
//   gm0        : [25000, 50025000)           (R,P,2S)
//   gc0        : [50025000, 50050000)        (R,P,2)
//   gm1        : [50050000, 100050000)
//   gc1        : [100050000, 100075000)

// Bucket-sorted filtration tables (built once per launch by bin_kernel)
__device__ float g_kx[SS], g_cx[SS];   // sorted-by-fx : key=fx, companion=fy
__device__ int   g_sx[SS];
__device__ float g_ky[SS], g_cy[SS];   // sorted-by-fy : key=fy, companion=fx
__device__ int   g_sy[SS];
__device__ int   g_ofx[NB + 1], g_ofy[NB + 1];

// One block per axis (blockIdx.x = axis), parallel prefix scan.
__global__ void bin_kernel(const float* __restrict__ filt)
{
    __shared__ int hist[NB];
    __shared__ int scan[NB];
    __shared__ int cur[NB];
    int t = threadIdx.x;
    int axis = blockIdx.x;

    hist[t] = 0;
    __syncthreads();
    for (int s = t; s < SS; s += NB) {
        float v = filt[2 * s + axis];
        int b = min(NB - 1, max(0, (int)floorf(v * (float)NB)));
        atomicAdd(&hist[b], 1);
    }
    __syncthreads();
    // inclusive scan (Hillis-Steele)
    int v = hist[t];
    scan[t] = v;
    __syncthreads();
    #pragma unroll
    for (int ofs = 1; ofs < NB; ofs <<= 1) {
        int add = (t >= ofs) ? scan[t - ofs] : 0;
        __syncthreads();
        scan[t] += add;
        __syncthreads();
    }
    int excl = scan[t] - v;
    int* offs = axis ? g_ofy : g_ofx;
    offs[t] = excl;
    if (t == NB - 1) offs[NB] = scan[t];
    cur[t] = excl;
    __syncthreads();
    for (int s = t; s < SS; s += NB) {
        float kv = filt[2 * s + axis];
        float cv = filt[2 * s + (1 - axis)];
        int b = min(NB - 1, max(0, (int)floorf(kv * (float)NB)));
        int pos = atomicAdd(&cur[b], 1);
        if (axis == 0) { g_kx[pos] = kv; g_cx[pos] = cv; g_sx[pos] = s; }
        else           { g_ky[pos] = kv; g_cy[pos] = cv; g_sy[pos] = s; }
    }
}

// One (h,r,p) row per block, 128 threads. Exactly 2 barriers per block.
//   phase 1: zero the 16KB row (8 x STG.128 per thread, MLP 8)
//   phase 2: all threads sweep the 10 candidate ranges (speculative loads)
__global__ __launch_bounds__(128) void grad_kernel(
    const float* __restrict__ bars0,
    const float* __restrict__ bars1,
    const float* __restrict__ pts,
    float* __restrict__ out)
{
    const size_t GM0 = 2ull * PP * RR;                     // 25000
    const size_t GC0 = GM0 + (size_t)RR * PP * 2 * SS;     // 50025000
    const size_t GM1 = GC0 + (size_t)RR * PP * 2;          // 50050000
    const size_t GC1 = GM1 + (size_t)RR * PP * 2 * SS;     // 100050000

    int b = blockIdx.x;
    int c = b / PP;            // combo 0..9 (p-major: adjacent blocks = adjacent rows)
    int p = b - c * PP;
    int h = c / RR, r = c - h * RR;
    int t = threadIdx.x;

    __shared__ unsigned sflags;

    float2 pt = ((const float2*)pts)[p];
    float ptx = pt.x, pty = pt.y;
    float psum = __fadd_rn(ptx, pty);

    float bar = (h ? bars1 : bars0)[p * RR + r];
    float sc  = __fadd_rn(bar, 0.01f);                  // scale = bar + GRID_RES

    if (t == 0) {
        sflags = 0u;
        out[(size_t)h * PP * RR + (size_t)p * RR + r] = bar;   // bars_stack
    }

    size_t rowbase = (h == 0 ? GM0 : GM1) +
                     ((size_t)r * PP + p) * (size_t)(2 * SS);

    // ---- Phase 1: zero the 16KB row ----
    float4* row4 = (float4*)(out + rowbase);
    const float4 z4 = make_float4(0.f, 0.f, 0.f, 0.f);
    #pragma unroll
    for (int i = 0; i < 8; ++i) {
        int idx = t + i * 128;
        if (idx < SS / 2) row4[idx] = z4;
    }
    __syncthreads();   // zeros (and sflags) visible before overwrite

    // ---- Phase 2: sparse scatter, all threads sweep each range ----
    unsigned mybits = 0u;
    #pragma unroll
    for (int rid = 0; rid < 10; ++rid) {
        int   axis = rid / 5;
        float kf   = (float)(rid % 5 - 2);
        float myp  = axis ? pty : ptx;       // line anchor for this axis
        float otp  = axis ? ptx : pty;       // companion axis anchor
        // Exact reference arithmetic (mul then add, no FMA fusion):
        float line  = __fadd_rn(__fmul_rn(kf, sc), myp);
        float lastc = __fadd_rn(__fmul_rn(2.0f, sc), otp); // last_{other axis}
        // Widened bucket range (max tol = 0.01001 < 0.0101)
        int b0 = min(NB - 1, max(0, (int)floorf((line - 0.0101f) * (float)NB)));
        int b1 = min(NB - 1, max(0, (int)floorf((line + 0.0101f) * (float)NB)));
        const int*   offs = axis ? g_ofy : g_ofx;
        const float* keys = axis ? g_ky  : g_kx;
        const float* comp = axis ? g_cy  : g_cx;
        const int*   sarr = axis ? g_sy  : g_sx;
        int lo = __ldg(&offs[b0]);
        int hi = __ldg(&offs[b1 + 1]);
        for (int i = lo + t; i < hi; i += 128) {
            // speculative parallel loads (all L1-resident), no chaining
            float key   = __ldg(&keys[i]);                     // f_axis[s]
            float other = __ldg(&comp[i]);                     // f_other[s]
            int   s     = __ldg(&sarr[i]);
            float tol = __fadd_rn(0.01f, __fmul_rn(1e-5f, fabsf(key)));
            bool hit = (fabsf(__fadd_rn(line, -key)) <= tol)   // close?
                    && (other <= lastc);                        // cond gate
            if (!hit) continue;
            float fsum = __fadd_rn(key, other);                // fx+fy (commutes)
            if (fsum == psum) continue;                        // value 0
            bool above = fsum > psum;
            out[rowbase + 2 * (size_t)s + (size_t)axis] = above ? 1.0f : -1.0f;
            mybits |= (axis ? 4u : 1u) << (above ? 0 : 1);
        }
    }
    if (mybits) atomicOr(&sflags, mybits);
    __syncthreads();

    if (t == 0) {
        unsigned fl = sflags;
        // cx = anyUpper ? -1 : anyLower ? 1 : 0   (signs flipped vs gm)
        float cxv = (fl & 1u) ? -1.0f : ((fl & 2u) ? 1.0f : 0.0f);
        float cyv = (fl & 4u) ? -1.0f : ((fl & 8u) ? 1.0f : 0.0f);
        size_t gcb = (h == 0 ? GC0 : GC1) + ((size_t)r * PP + p) * 2;
        out[gcb]     = cxv;
        out[gcb + 1] = cyv;
    }
}

extern "C" void kernel_launch(void* const* d_in, const int* in_sizes, int n_in,
                              void* d_out, int out_size)
{
    (void)in_sizes; (void)n_in; (void)out_size;
    const float* filtration = (const float*)d_in[0];   // (S,2)
    const float* bars0      = (const float*)d_in[1];   // (P,R)
    const float* bars1      = (const float*)d_in[2];   // (P,R)
    const float* pts        = (const float*)d_in[3];   // (P,2)
    float* out = (float*)d_out;

    bin_kernel<<<2, NB>>>(filtration);
    grad_kernel<<<10 * PP, 128>>>(bars0, bars1, pts, out);
}

// round 6
// speedup vs baseline: 2.3320x; 1.1266x over previous
#include <cuda_runtime.h>
#include <cuda_bf16.h>

// Problem constants (fixed by setup_inputs)
#define SS 2000   // filtration points
#define PP 2500   // sample points
#define RR 5      // bars per point
#define NB 256    // buckets for counting sort

// Output layout (flattened concatenation, floats):
//   bars_stack : [0, 25000)
//   gm0        : [25000, 50025000)           (R,P,2S)
//   gc0        : [50025000, 50050000)        (R,P,2)
//   gm1        : [50050000, 100050000)
//   gc1        : [100050000, 100075000)

// Bucket-sorted packed tables: {key, companion, s_as_float_bits, tol}
__device__ float4 g_px[SS];            // sorted by fx
__device__ float4 g_py[SS];            // sorted by fy
__device__ int    g_ofx[NB + 1], g_ofy[NB + 1];

// One block per axis (blockIdx.x = axis), parallel prefix scan.
__global__ void bin_kernel(const float* __restrict__ filt)
{
    __shared__ int hist[NB];
    __shared__ int scan[NB];
    __shared__ int cur[NB];
    int t = threadIdx.x;
    int axis = blockIdx.x;

    hist[t] = 0;
    __syncthreads();
    for (int s = t; s < SS; s += NB) {
        float v = filt[2 * s + axis];
        int b = min(NB - 1, max(0, (int)floorf(v * (float)NB)));
        atomicAdd(&hist[b], 1);
    }
    __syncthreads();
    // inclusive scan (Hillis-Steele)
    int v = hist[t];
    scan[t] = v;
    __syncthreads();
    #pragma unroll
    for (int ofs = 1; ofs < NB; ofs <<= 1) {
        int add = (t >= ofs) ? scan[t - ofs] : 0;
        __syncthreads();
        scan[t] += add;
        __syncthreads();
    }
    int excl = scan[t] - v;
    int* offs = axis ? g_ofy : g_ofx;
    offs[t] = excl;
    if (t == NB - 1) offs[NB] = scan[t];
    cur[t] = excl;
    __syncthreads();
    float4* tab = axis ? g_py : g_px;
    for (int s = t; s < SS; s += NB) {
        float kv = filt[2 * s + axis];
        float cv = filt[2 * s + (1 - axis)];
        int b = min(NB - 1, max(0, (int)floorf(kv * (float)NB)));
        int pos = atomicAdd(&cur[b], 1);
        // tol with the exact reference arithmetic (no FMA fusion)
        float tol = __fadd_rn(0.01f, __fmul_rn(1e-5f, fabsf(kv)));
        tab[pos] = make_float4(kv, cv, __int_as_float(s), tol);
    }
}

// One (h,r,p) row per block, 128 threads = 4 warps. 2 barriers per block.
//   phase 1: zero the 16KB row (8 x STG.128 per thread, MLP 8)
//   phase 2: warp w sweeps ranges w, w+4, w+8 (packed LDG.128 candidates)
__global__ __launch_bounds__(128) void grad_kernel(
    const float* __restrict__ bars0,
    const float* __restrict__ bars1,
    const float* __restrict__ pts,
    float* __restrict__ out)
{
    const size_t GM0 = 2ull * PP * RR;                     // 25000
    const size_t GC0 = GM0 + (size_t)RR * PP * 2 * SS;     // 50025000
    const size_t GM1 = GC0 + (size_t)RR * PP * 2;          // 50050000
    const size_t GC1 = GM1 + (size_t)RR * PP * 2 * SS;     // 100050000

    int b = blockIdx.x;
    int c = b / PP;            // combo 0..9 (p-major: adjacent blocks = adjacent rows)
    int p = b - c * PP;
    int h = c / RR, r = c - h * RR;
    int t = threadIdx.x;
    int warp = t >> 5, lane = t & 31;

    __shared__ unsigned sflags;

    float2 pt = ((const float2*)pts)[p];
    float ptx = pt.x, pty = pt.y;
    float psum = __fadd_rn(ptx, pty);

    float bar = (h ? bars1 : bars0)[p * RR + r];
    float sc  = __fadd_rn(bar, 0.01f);                  // scale = bar + GRID_RES

    if (t == 0) {
        sflags = 0u;
        out[(size_t)h * PP * RR + (size_t)p * RR + r] = bar;   // bars_stack
    }

    size_t rowbase = (h == 0 ? GM0 : GM1) +
                     ((size_t)r * PP + p) * (size_t)(2 * SS);

    // ---- Phase 1: zero the 16KB row ----
    float4* row4 = (float4*)(out + rowbase);
    const float4 z4 = make_float4(0.f, 0.f, 0.f, 0.f);
    #pragma unroll
    for (int i = 0; i < 8; ++i) {
        int idx = t + i * 128;
        if (idx < SS / 2) row4[idx] = z4;
    }
    __syncthreads();   // zeros (and sflags) visible before overwrite

    // ---- Phase 2: warp-owned sparse scatter over 10 ranges ----
    unsigned mybits = 0u;
    for (int rid = warp; rid < 10; rid += 4) {
        int   axis = rid / 5;
        float kf   = (float)(rid % 5 - 2);
        float myp  = axis ? pty : ptx;       // line anchor for this axis
        float otp  = axis ? ptx : pty;       // companion axis anchor
        // Exact reference arithmetic (mul then add, no FMA fusion):
        float line  = __fadd_rn(__fmul_rn(kf, sc), myp);
        float lastc = __fadd_rn(__fmul_rn(2.0f, sc), otp); // last_{other axis}
        // Widened bucket range (max tol = 0.01001 < 0.0101)
        int b0 = min(NB - 1, max(0, (int)floorf((line - 0.0101f) * (float)NB)));
        int b1 = min(NB - 1, max(0, (int)floorf((line + 0.0101f) * (float)NB)));
        const int*    offs = axis ? g_ofy : g_ofx;
        const float4* tab  = axis ? g_py  : g_px;
        int lo = __ldg(&offs[b0]);
        int hi = __ldg(&offs[b1 + 1]);
        for (int i = lo + lane; i < hi; i += 32) {
            float4 e = __ldg(&tab[i]);          // {key, comp, s_bits, tol}
            bool hit = (fabsf(__fadd_rn(line, -e.x)) <= e.w)   // close?
                    && (e.y <= lastc);                          // cond gate
            if (!hit) continue;
            float fsum = __fadd_rn(e.x, e.y);                  // fx+fy (commutes)
            if (fsum == psum) continue;                        // value 0
            bool above = fsum > psum;
            int s = __float_as_int(e.z);
            out[rowbase + 2 * (size_t)s + (size_t)axis] = above ? 1.0f : -1.0f;
            mybits |= (axis ? 4u : 1u) << (above ? 0 : 1);
        }
    }
    mybits = __reduce_or_sync(0xffffffffu, mybits);
    if (lane == 0 && mybits) atomicOr(&sflags, mybits);
    __syncthreads();

    if (t == 0) {
        unsigned fl = sflags;
        // cx = anyUpper ? -1 : anyLower ? 1 : 0   (signs flipped vs gm)
        float cxv = (fl & 1u) ? -1.0f : ((fl & 2u) ? 1.0f : 0.0f);
        float cyv = (fl & 4u) ? -1.0f : ((fl & 8u) ? 1.0f : 0.0f);
        size_t gcb = (h == 0 ? GC0 : GC1) + ((size_t)r * PP + p) * 2;
        out[gcb]     = cxv;
        out[gcb + 1] = cyv;
    }
}

extern "C" void kernel_launch(void* const* d_in, const int* in_sizes, int n_in,
                              void* d_out, int out_size)
{
    (void)in_sizes; (void)n_in; (void)out_size;
    const float* filtration = (const float*)d_in[0];   // (S,2)
    const float* bars0      = (const float*)d_in[1];   // (P,R)
    const float* bars1      = (const float*)d_in[2];   // (P,R)
    const float* pts        = (const float*)d_in[3];   // (P,2)
    float* out = (float*)d_out;

    bin_kernel<<<2, NB>>>(filtration);
    grad_kernel<<<10 * PP, 128>>>(bars0, bars1, pts, out);
}

// round 7
// speedup vs baseline: 2.3495x; 1.0075x over previous
#include <cuda_runtime.h>
#include <cuda_bf16.h>

// Problem constants (fixed by setup_inputs)
#define SS 2000   // filtration points
#define PP 2500   // sample points
#define RR 5      // bars per point
#define NB 256    // buckets for counting sort

// Output layout (flattened concatenation, floats):
//   bars_stack : [0, 25000)
//   gm0        : [25000, 50025000)           (R,P,2S)
//   gc0        : [50025000, 50050000)        (R,P,2)
//   gm1        : [50050000, 100050000)
//   gc1        : [100050000, 100075000)

// Bucket-sorted packed tables: {key, companion, s_as_float_bits, tol}
__device__ float4 g_px[SS];            // sorted by fx
__device__ float4 g_py[SS];            // sorted by fy
__device__ int    g_ofx[NB + 1], g_ofy[NB + 1];

// One block per axis (blockIdx.x = axis), parallel prefix scan.
__global__ void bin_kernel(const float* __restrict__ filt)
{
    __shared__ int hist[NB];
    __shared__ int scan[NB];
    __shared__ int cur[NB];
    int t = threadIdx.x;
    int axis = blockIdx.x;

    hist[t] = 0;
    __syncthreads();
    for (int s = t; s < SS; s += NB) {
        float v = filt[2 * s + axis];
        int b = min(NB - 1, max(0, (int)floorf(v * (float)NB)));
        atomicAdd(&hist[b], 1);
    }
    __syncthreads();
    // inclusive scan (Hillis-Steele)
    int v = hist[t];
    scan[t] = v;
    __syncthreads();
    #pragma unroll
    for (int ofs = 1; ofs < NB; ofs <<= 1) {
        int add = (t >= ofs) ? scan[t - ofs] : 0;
        __syncthreads();
        scan[t] += add;
        __syncthreads();
    }
    int excl = scan[t] - v;
    int* offs = axis ? g_ofy : g_ofx;
    offs[t] = excl;
    if (t == NB - 1) offs[NB] = scan[t];
    cur[t] = excl;
    __syncthreads();
    float4* tab = axis ? g_py : g_px;
    for (int s = t; s < SS; s += NB) {
        float kv = filt[2 * s + axis];
        float cv = filt[2 * s + (1 - axis)];
        int b = min(NB - 1, max(0, (int)floorf(kv * (float)NB)));
        int pos = atomicAdd(&cur[b], 1);
        // tol with the exact reference arithmetic (no FMA fusion)
        float tol = __fadd_rn(0.01f, __fmul_rn(1e-5f, fabsf(kv)));
        tab[pos] = make_float4(kv, cv, __int_as_float(s), tol);
    }
}

// One (h,r,p) row per block, 128 threads = 4 warps.
// Row assembled in SMEM; GMEM written exactly once (coalesced STG.128).
//   phase 1: zero 16KB smem row (STS.128)
//   phase 2: warp w sweeps ranges w, w+4, w+8; scattered STS.32 into smem
//   phase 3: single coalesced smem -> gmem copy
__global__ __launch_bounds__(128) void grad_kernel(
    const float* __restrict__ bars0,
    const float* __restrict__ bars1,
    const float* __restrict__ pts,
    float* __restrict__ out)
{
    const size_t GM0 = 2ull * PP * RR;                     // 25000
    const size_t GC0 = GM0 + (size_t)RR * PP * 2 * SS;     // 50025000
    const size_t GM1 = GC0 + (size_t)RR * PP * 2;          // 50050000
    const size_t GC1 = GM1 + (size_t)RR * PP * 2 * SS;     // 100050000

    __shared__ __align__(16) float srow[2 * SS];   // 16 KB row buffer
    __shared__ unsigned sflags;

    int b = blockIdx.x;
    int c = b / PP;            // combo 0..9 (p-major: adjacent blocks = adjacent rows)
    int p = b - c * PP;
    int h = c / RR, r = c - h * RR;
    int t = threadIdx.x;
    int warp = t >> 5, lane = t & 31;

    float2 pt = ((const float2*)pts)[p];
    float ptx = pt.x, pty = pt.y;
    float psum = __fadd_rn(ptx, pty);

    float bar = (h ? bars1 : bars0)[p * RR + r];
    float sc  = __fadd_rn(bar, 0.01f);                  // scale = bar + GRID_RES

    if (t == 0) {
        sflags = 0u;
        out[(size_t)h * PP * RR + (size_t)p * RR + r] = bar;   // bars_stack
    }

    // ---- Phase 1: zero the smem row ----
    float4* s4 = (float4*)srow;
    const float4 z4 = make_float4(0.f, 0.f, 0.f, 0.f);
    #pragma unroll
    for (int i = 0; i < 8; ++i) {
        int idx = t + i * 128;
        if (idx < SS / 2) s4[idx] = z4;
    }
    __syncthreads();

    // ---- Phase 2: warp-owned sparse scatter into smem ----
    unsigned mybits = 0u;
    for (int rid = warp; rid < 10; rid += 4) {
        int   axis = rid / 5;
        float kf   = (float)(rid % 5 - 2);
        float myp  = axis ? pty : ptx;       // line anchor for this axis
        float otp  = axis ? ptx : pty;       // companion axis anchor
        // Exact reference arithmetic (mul then add, no FMA fusion):
        float line  = __fadd_rn(__fmul_rn(kf, sc), myp);
        float lastc = __fadd_rn(__fmul_rn(2.0f, sc), otp); // last_{other axis}
        // Widened bucket range (max tol = 0.01001 < 0.0101)
        int b0 = min(NB - 1, max(0, (int)floorf((line - 0.0101f) * (float)NB)));
        int b1 = min(NB - 1, max(0, (int)floorf((line + 0.0101f) * (float)NB)));
        const int*    offs = axis ? g_ofy : g_ofx;
        const float4* tab  = axis ? g_py  : g_px;
        int lo = __ldg(&offs[b0]);
        int hi = __ldg(&offs[b1 + 1]);
        for (int i = lo + lane; i < hi; i += 32) {
            float4 e = __ldg(&tab[i]);          // {key, comp, s_bits, tol}
            bool hit = (fabsf(__fadd_rn(line, -e.x)) <= e.w)   // close?
                    && (e.y <= lastc);                          // cond gate
            if (!hit) continue;
            float fsum = __fadd_rn(e.x, e.y);                  // fx+fy (commutes)
            if (fsum == psum) continue;                        // value 0
            bool above = fsum > psum;
            int s = __float_as_int(e.z);
            srow[2 * s + axis] = above ? 1.0f : -1.0f;
            mybits |= (axis ? 4u : 1u) << (above ? 0 : 1);
        }
    }
    mybits = __reduce_or_sync(0xffffffffu, mybits);
    if (lane == 0 && mybits) atomicOr(&sflags, mybits);
    __syncthreads();

    // ---- Phase 3: single coalesced smem -> gmem copy ----
    size_t rowbase = (h == 0 ? GM0 : GM1) +
                     ((size_t)r * PP + p) * (size_t)(2 * SS);
    float4* row4 = (float4*)(out + rowbase);
    #pragma unroll
    for (int i = 0; i < 8; ++i) {
        int idx = t + i * 128;
        if (idx < SS / 2) row4[idx] = s4[idx];
    }

    if (t == 0) {
        unsigned fl = sflags;
        // cx = anyUpper ? -1 : anyLower ? 1 : 0   (signs flipped vs gm)
        float cxv = (fl & 1u) ? -1.0f : ((fl & 2u) ? 1.0f : 0.0f);
        float cyv = (fl & 4u) ? -1.0f : ((fl & 8u) ? 1.0f : 0.0f);
        size_t gcb = (h == 0 ? GC0 : GC1) + ((size_t)r * PP + p) * 2;
        out[gcb]     = cxv;
        out[gcb + 1] = cyv;
    }
}

extern "C" void kernel_launch(void* const* d_in, const int* in_sizes, int n_in,
                              void* d_out, int out_size)
{
    (void)in_sizes; (void)n_in; (void)out_size;
    const float* filtration = (const float*)d_in[0];   // (S,2)
    const float* bars0      = (const float*)d_in[1];   // (P,R)
    const float* bars1      = (const float*)d_in[2];   // (P,R)
    const float* pts        = (const float*)d_in[3];   // (P,2)
    float* out = (float*)d_out;

    bin_kernel<<<2, NB>>>(filtration);
    grad_kernel<<<10 * PP, 128>>>(bars0, bars1, pts, out);
}